// round 11
// baseline (speedup 1.0000x reference)
#include <cuda_runtime.h>
#include <math.h>
#include <stdint.h>

#define BATCH 4
#define NTOK  2048
#define DMODEL 1024
#define HEADS 16
#define DH    64
#define INNER 1024
#define SCALE 0.125f                 /* 64^-0.5 */
#define CLOG2E 0.1803368801111f      /* SCALE * log2(e) */
#define TWO_C  0.3606737602222f      /* 2 * SCALE * log2(e) */

typedef unsigned long long u64;

__device__ __forceinline__ u64 pack2(float x) {
    u64 r; asm("mov.b64 %0, {%1, %1};" : "=l"(r) : "f"(x)); return r;
}
__device__ __forceinline__ float2 unpack2(u64 a) {
    float2 f; asm("mov.b64 {%0, %1}, %2;" : "=f"(f.x), "=f"(f.y) : "l"(a)); return f;
}
__device__ __forceinline__ void ffma2(u64 &d, u64 a, u64 b) {
    asm("fma.rn.f32x2 %0, %1, %2, %0;" : "+l"(d) : "l"(a), "l"(b));
}
__device__ __forceinline__ uint32_t smem_u32(const void* p) {
    uint32_t a;
    asm("{ .reg .u64 t; cvta.to.shared.u64 t, %1; cvt.u32.u64 %0, t; }"
        : "=r"(a) : "l"(p));
    return a;
}
__device__ __forceinline__ void cp_async16(uint32_t dst, const void* src) {
    asm volatile("cp.async.cg.shared.global [%0], [%1], 16;"
                 :: "r"(dst), "l"(src) : "memory");
}
__device__ __forceinline__ void cp_commit() {
    asm volatile("cp.async.commit_group;" ::: "memory");
}
__device__ __forceinline__ void cp_wait0() {
    asm volatile("cp.async.wait_group 0;" ::: "memory");
}

// Scratch (allocation-free rule: __device__ globals)
__device__ float g_q[BATCH * NTOK * INNER];
__device__ float g_v[BATCH * NTOK * INNER];
__device__ float g_ao[BATCH * NTOK * INNER];
__device__ float g_norm[BATCH * HEADS * NTOK];   // ‖q‖² * SCALE * log2e

// ---------------------------------------------------------------------------
// SGEMM (f32x2, BK=16, duplicated-A smem => zero pack MOVs, cp.async B,
// double-buffered, one barrier per stage, dual-output):
//   set = blockIdx.x >> 3 selects {W0,b0,C0} or {W1,b1,C1} (same A).
// ---------------------------------------------------------------------------
#define BK     16
#define AS_ROW 264                     /* 2*128 dup + pad, floats per k-row */
#define AS_ST  (BK * AS_ROW)           /* 4224 floats per stage */
#define BS_ST  (BK * 128)              /* 2048 floats per stage */
#define GSMEM  ((2 * AS_ST + 2 * BS_ST) * 4)   /* 50176 B */

__global__ __launch_bounds__(256, 2) void sgemm_dual(
    const float* __restrict__ A,
    const float* __restrict__ W0, const float* __restrict__ b0, float* __restrict__ C0,
    const float* __restrict__ W1, const float* __restrict__ b1, float* __restrict__ C1,
    int M, int N, int K)
{
    extern __shared__ float sm[];
    float* As2 = sm;                    // [stage][k][2m dup]
    float* Bsm = sm + 2 * AS_ST;        // [stage][k][n]
    const uint32_t bs_base = smem_u32(Bsm);

    const int tid = threadIdx.x;
    const int set = blockIdx.x >> 3;
    const int bn = (blockIdx.x & 7) * 128;
    const int bm = blockIdx.y * 128;
    const int tx = tid & 15;
    const int ty = tid >> 4;

    const float* W    = set ? W1 : W0;
    const float* bias = set ? b1 : b0;
    float*       C    = set ? C1 : C0;

    // A load mapping: 2 float4 per thread per stage. idx = tid*2+c:
    //   m = idx>>2 (0..127), kg = (idx&3)*4
    const int am0 = tid >> 1;
    const int akg0 = (tid & 1) * 8;           // c=0 -> kg=(2t&3)*4; c=1 -> +4? recompute below
    // B cp.async mapping: idx = tid*2+c: row = idx>>5, col = (idx&31)*4
    (void)akg0; (void)am0;

    u64 acc[8][4];
    #pragma unroll
    for (int i = 0; i < 8; i++)
        #pragma unroll
        for (int j = 0; j < 4; j++) acc[i][j] = 0ull;

    const int nst = K / BK;   // 64

    // ---- helpers as lambdas ----
    auto issue_B = [&](int s, int buf) {
        #pragma unroll
        for (int c = 0; c < 2; c++) {
            int idx = tid * 2 + c;
            int row = idx >> 5;
            int col = (idx & 31) * 4;
            cp_async16(bs_base + (uint32_t)((buf * BS_ST + row * 128 + col) * 4),
                       W + (size_t)(s * BK + row) * N + bn + col);
        }
        cp_commit();
    };
    auto load_A = [&](int s, float4* r) {
        #pragma unroll
        for (int c = 0; c < 2; c++) {
            int idx = tid * 2 + c;
            int m = idx >> 2;
            int kg = (idx & 3) * 4;
            r[c] = *(const float4*)(A + (size_t)(bm + m) * K + s * BK + kg);
        }
    };
    auto store_A = [&](int buf, const float4* r) {
        #pragma unroll
        for (int c = 0; c < 2; c++) {
            int idx = tid * 2 + c;
            int m = idx >> 2;
            int kg = (idx & 3) * 4;
            float* base = As2 + buf * AS_ST + 2 * m;
            const float vs[4] = {r[c].x, r[c].y, r[c].z, r[c].w};
            #pragma unroll
            for (int e = 0; e < 4; e++)
                *(float2*)(base + (kg + e) * AS_ROW) = make_float2(vs[e], vs[e]);
        }
    };

    // ---- prologue: stage 0 into buffer 0 ----
    {
        float4 a0[2];
        issue_B(0, 0);
        load_A(0, a0);
        store_A(0, a0);
        cp_wait0();
        __syncthreads();
    }

    for (int s = 0; s < nst; s++) {
        const int cur = s & 1;
        const bool more = (s + 1 < nst);
        float4 apf[2];
        if (more) {
            issue_B(s + 1, cur ^ 1);
            load_A(s + 1, apf);
        }

        const float* Ac = As2 + cur * AS_ST + 16 * ty;
        const float* Bc = Bsm + cur * BS_ST + tx * 4;
        #pragma unroll
        for (int kk = 0; kk < BK; kk++) {
            alignas(16) u64 ad[8];
            *(float4*)&ad[0] = *(const float4*)(Ac + kk * AS_ROW);
            *(float4*)&ad[2] = *(const float4*)(Ac + kk * AS_ROW + 4);
            *(float4*)&ad[4] = *(const float4*)(Ac + kk * AS_ROW + 8);
            *(float4*)&ad[6] = *(const float4*)(Ac + kk * AS_ROW + 12);
            alignas(16) u64 b2[4];
            *(float4*)&b2[0] = *(const float4*)(Bc + kk * 128);
            *(float4*)&b2[2] = *(const float4*)(Bc + kk * 128 + 64);
            #pragma unroll
            for (int i = 0; i < 8; i++)
                #pragma unroll
                for (int j = 0; j < 4; j++)
                    ffma2(acc[i][j], ad[i], b2[j]);
        }

        if (more) {
            store_A(cur ^ 1, apf);
            cp_wait0();
            __syncthreads();
        }
    }

    float4 bb0 = *(const float4*)(bias + bn + tx * 4);
    float4 bb1 = *(const float4*)(bias + bn + 64 + tx * 4);

    #pragma unroll
    for (int i = 0; i < 8; i++) {
        float* Cp = C + (size_t)(bm + ty * 8 + i) * N + bn;
        float2 p0 = unpack2(acc[i][0]), p1 = unpack2(acc[i][1]);
        float2 p2 = unpack2(acc[i][2]), p3 = unpack2(acc[i][3]);
        float4 o0 = make_float4(p0.x + bb0.x, p0.y + bb0.y, p1.x + bb0.z, p1.y + bb0.w);
        float4 o1 = make_float4(p2.x + bb1.x, p2.y + bb1.y, p3.x + bb1.z, p3.y + bb1.w);
        *(float4*)(Cp + tx * 4) = o0;
        *(float4*)(Cp + 64 + tx * 4) = o1;
    }
}

// ---------------------------------------------------------------------------
// Row norms, pre-scaled by SCALE*log2(e)
// ---------------------------------------------------------------------------
__global__ __launch_bounds__(256) void compute_norms(
    const float* __restrict__ q, float* __restrict__ norms)
{
    int idx = blockIdx.x * 256 + threadIdx.x;
    int n  = idx & (NTOK - 1);
    int bh = idx >> 11;
    int h = bh & (HEADS - 1);
    int b = bh >> 4;
    const float* p = q + ((size_t)(b * NTOK + n)) * INNER + h * DH;
    float s = 0.f;
    #pragma unroll
    for (int d = 0; d < DH; d += 4) {
        float4 t = *(const float4*)(p + d);
        s += t.x * t.x + t.y * t.y + t.z * t.z + t.w * t.w;
    }
    norms[idx] = s * CLOG2E;
}

// ---------------------------------------------------------------------------
// Flash attention (k=q), f32x2, no online softmax (R9-proven)
// ---------------------------------------------------------------------------
#define QSTR 132
#define KSTR 68
#define VSTR 68
#define PSTR 132

__global__ __launch_bounds__(256) void attn_kernel(
    const float* __restrict__ q, const float* __restrict__ v,
    const float* __restrict__ norms, float* __restrict__ ao)
{
    extern __shared__ float sma[];
    float* Qs = sma;
    float* Ks = Qs + 64 * QSTR;
    float* Vs = Ks + 64 * KSTR;
    float* Ps = Vs + 64 * VSTR;
    float* kn = Ps + 64 * PSTR;

    const int tid = threadIdx.x;
    const int tx = tid & 15;
    const int ty = tid >> 4;
    const int i0 = blockIdx.x * 128;
    const int bh = blockIdx.y;
    const int h = bh & (HEADS - 1);
    const int b = bh >> 4;

    const float* qb = q + (size_t)b * NTOK * INNER + h * DH;
    const float* vb = v + (size_t)b * NTOK * INNER + h * DH;
    const float* nb = norms + (size_t)bh * NTOK;

    #pragma unroll
    for (int it = 0; it < 8; it++) {
        int idx = tid + it * 256;
        int r = idx >> 4;
        int d = (idx & 15) * 4;
        float4 t = *(const float4*)(qb + (size_t)(i0 + r) * INNER + d);
        Qs[(d + 0) * QSTR + r] = t.x;
        Qs[(d + 1) * QSTR + r] = t.y;
        Qs[(d + 2) * QSTR + r] = t.z;
        Qs[(d + 3) * QSTR + r] = t.w;
    }

    float aaC[8], lsum[8];
    #pragma unroll
    for (int r = 0; r < 8; r++) {
        aaC[r] = __ldg(nb + i0 + ty * 8 + r);
        lsum[r] = 0.f;
    }

    u64 acco[4][4];
    #pragma unroll
    for (int ip = 0; ip < 4; ip++)
        #pragma unroll
        for (int c = 0; c < 4; c++) acco[ip][c] = 0ull;

    for (int j0 = 0; j0 < NTOK; j0 += 64) {
        __syncthreads();

        #pragma unroll
        for (int it = 0; it < 4; it++) {
            int idx = tid + it * 256;
            int r = idx >> 4;
            int d = (idx & 15) * 4;
            float4 kt = *(const float4*)(qb + (size_t)(j0 + r) * INNER + d);
            Ks[(d + 0) * KSTR + r] = kt.x;
            Ks[(d + 1) * KSTR + r] = kt.y;
            Ks[(d + 2) * KSTR + r] = kt.z;
            Ks[(d + 3) * KSTR + r] = kt.w;
            float4 vt = *(const float4*)(vb + (size_t)(j0 + r) * INNER + d);
            *(float4*)&Vs[r * VSTR + d] = vt;
        }
        if (tid < 64) kn[tid] = nb[j0 + tid];
        __syncthreads();

        u64 accs[4][4];
        #pragma unroll
        for (int ip = 0; ip < 4; ip++)
            #pragma unroll
            for (int c = 0; c < 4; c++) accs[ip][c] = 0ull;

        #pragma unroll 4
        for (int kk = 0; kk < 64; kk++) {
            alignas(16) u64 a2[4];
            *(float4*)&a2[0] = *(const float4*)&Qs[kk * QSTR + ty * 8];
            *(float4*)&a2[2] = *(const float4*)&Qs[kk * QSTR + ty * 8 + 4];
            float4 kv = *(const float4*)&Ks[kk * KSTR + tx * 4];
            u64 b2[4];
            b2[0] = pack2(kv.x); b2[1] = pack2(kv.y);
            b2[2] = pack2(kv.z); b2[3] = pack2(kv.w);
            #pragma unroll
            for (int ip = 0; ip < 4; ip++)
                #pragma unroll
                for (int c = 0; c < 4; c++)
                    ffma2(accs[ip][c], a2[ip], b2[c]);
        }

        float bbC[4];
        #pragma unroll
        for (int c = 0; c < 4; c++) bbC[c] = kn[tx * 4 + c];

        float p[8][4];
        #pragma unroll
        for (int ip = 0; ip < 4; ip++) {
            const float a0 = aaC[2 * ip], a1 = aaC[2 * ip + 1];
            #pragma unroll
            for (int c = 0; c < 4; c++) {
                float2 t = unpack2(accs[ip][c]);
                float p0 = exp2f(fmaf(t.x, TWO_C, -a0) - bbC[c]);
                float p1 = exp2f(fmaf(t.y, TWO_C, -a1) - bbC[c]);
                p[2 * ip][c] = p0;
                p[2 * ip + 1][c] = p1;
                lsum[2 * ip] += p0;
                lsum[2 * ip + 1] += p1;
            }
        }

        __syncthreads();

        #pragma unroll
        for (int c = 0; c < 4; c++) {
            int j = tx * 4 + c;
            float4 p0 = make_float4(p[0][c], p[1][c], p[2][c], p[3][c]);
            float4 p1 = make_float4(p[4][c], p[5][c], p[6][c], p[7][c]);
            *(float4*)&Ps[j * PSTR + ty * 8] = p0;
            *(float4*)&Ps[j * PSTR + ty * 8 + 4] = p1;
        }
        __syncthreads();

        #pragma unroll 2
        for (int j = 0; j < 64; j++) {
            alignas(16) u64 p2[4];
            *(float4*)&p2[0] = *(const float4*)&Ps[j * PSTR + ty * 8];
            *(float4*)&p2[2] = *(const float4*)&Ps[j * PSTR + ty * 8 + 4];
            float4 vv = *(const float4*)&Vs[j * VSTR + tx * 4];
            u64 v2[4];
            v2[0] = pack2(vv.x); v2[1] = pack2(vv.y);
            v2[2] = pack2(vv.z); v2[3] = pack2(vv.w);
            #pragma unroll
            for (int ip = 0; ip < 4; ip++)
                #pragma unroll
                for (int c = 0; c < 4; c++)
                    ffma2(acco[ip][c], p2[ip], v2[c]);
        }
    }

    float inv[8];
    #pragma unroll
    for (int r = 0; r < 8; r++) {
        float lv = lsum[r];
        #pragma unroll
        for (int off = 8; off > 0; off >>= 1)
            lv += __shfl_xor_sync(0xffffffffu, lv, off);
        inv[r] = 1.f / lv;
    }

    float* ob = ao + ((size_t)b * NTOK + i0) * INNER + h * DH;
    #pragma unroll
    for (int ip = 0; ip < 4; ip++) {
        float2 o0 = unpack2(acco[ip][0]);
        float2 o1 = unpack2(acco[ip][1]);
        float2 o2 = unpack2(acco[ip][2]);
        float2 o3 = unpack2(acco[ip][3]);
        int r0 = ty * 8 + 2 * ip;
        float inv0 = inv[2 * ip];
        float inv1 = inv[2 * ip + 1];
        float4 w0 = make_float4(o0.x * inv0, o1.x * inv0, o2.x * inv0, o3.x * inv0);
        float4 w1 = make_float4(o0.y * inv1, o1.y * inv1, o2.y * inv1, o3.y * inv1);
        *(float4*)(ob + (size_t)r0 * INNER + tx * 4) = w0;
        *(float4*)(ob + (size_t)(r0 + 1) * INNER + tx * 4) = w1;
    }
}

// ---------------------------------------------------------------------------
extern "C" void kernel_launch(void* const* d_in, const int* in_sizes, int n_in,
                              void* d_out, int out_size)
{
    const float* x  = (const float*)d_in[0];
    const float* Wq = (const float*)d_in[1];
    const float* bq = (const float*)d_in[2];
    const float* Wv = (const float*)d_in[3];
    const float* bv = (const float*)d_in[4];
    const float* Wo = (const float*)d_in[5];
    const float* bo = (const float*)d_in[6];
    float* out = (float*)d_out;

    float *qp, *vp, *aop, *np;
    cudaGetSymbolAddress((void**)&qp,  g_q);
    cudaGetSymbolAddress((void**)&vp,  g_v);
    cudaGetSymbolAddress((void**)&aop, g_ao);
    cudaGetSymbolAddress((void**)&np,  g_norm);

    const int M = BATCH * NTOK;   // 8192

    cudaFuncSetAttribute(sgemm_dual,
                         cudaFuncAttributeMaxDynamicSharedMemorySize, GSMEM);

    // fused q+v projection: blocks 0..7 -> Wq/q, 8..15 -> Wv/v
    sgemm_dual<<<dim3(16, M / 128), 256, GSMEM>>>(
        x, Wq, bq, qp, Wv, bv, vp, M, INNER, DMODEL);

    compute_norms<<<(BATCH * HEADS * NTOK) / 256, 256>>>(qp, np);

    int asmem = (64 * QSTR + 64 * KSTR + 64 * VSTR + 64 * PSTR + 64) * (int)sizeof(float);
    cudaFuncSetAttribute(attn_kernel,
                         cudaFuncAttributeMaxDynamicSharedMemorySize, asmem);
    attn_kernel<<<dim3(NTOK / 128, BATCH * HEADS), 256, asmem>>>(qp, vp, np, aop);

    // output projection (single set: both slots point at Wo)
    sgemm_dual<<<dim3(8, M / 128), 256, GSMEM>>>(
        aop, Wo, bo, out, Wo, bo, out, M, DMODEL, INNER);
}

// round 12
// speedup vs baseline: 1.0827x; 1.0827x over previous
#include <cuda_runtime.h>
#include <math.h>

#define BATCH 4
#define NTOK  2048
#define DMODEL 1024
#define HEADS 16
#define DH    64
#define INNER 1024
#define SCALE 0.125f                 /* 64^-0.5 */
#define CLOG2E 0.1803368801111f      /* SCALE * log2(e) */
#define TWO_C  0.3606737602222f      /* 2 * SCALE * log2(e) */

typedef unsigned long long u64;

__device__ __forceinline__ u64 pack2(float x) {
    u64 r; asm("mov.b64 %0, {%1, %1};" : "=l"(r) : "f"(x)); return r;
}
__device__ __forceinline__ float2 unpack2(u64 a) {
    float2 f; asm("mov.b64 {%0, %1}, %2;" : "=f"(f.x), "=f"(f.y) : "l"(a)); return f;
}
__device__ __forceinline__ void ffma2(u64 &d, u64 a, u64 b) {
    asm("fma.rn.f32x2 %0, %1, %2, %0;" : "+l"(d) : "l"(a), "l"(b));
}

// Scratch (allocation-free rule: __device__ globals)
__device__ float g_q[BATCH * NTOK * INNER];
__device__ float g_v[BATCH * NTOK * INNER];
__device__ float g_ao[BATCH * NTOK * INNER];
__device__ float g_norm[BATCH * HEADS * NTOK];   // ‖q‖² * SCALE * log2e

// ---------------------------------------------------------------------------
// SGEMM (f32x2, double-buffered, dual-output) — R10-proven version.
//   set = blockIdx.x >> 3 selects {W0,b0,C0} or {W1,b1,C1} (same A).
//   C[M,1024] = A[M,K] @ W[K,1024] + b.  One __syncthreads per K-stage.
// ---------------------------------------------------------------------------
__global__ __launch_bounds__(256, 2) void sgemm_dual(
    const float* __restrict__ A,
    const float* __restrict__ W0, const float* __restrict__ b0, float* __restrict__ C0,
    const float* __restrict__ W1, const float* __restrict__ b1, float* __restrict__ C1,
    int M, int N, int K)
{
    __shared__ float As[2][8][128];   // [stage][k][m] transposed
    __shared__ float Bs[2][8][128];   // [stage][k][n]

    const int tid = threadIdx.x;
    const int set = blockIdx.x >> 3;
    const int bn = (blockIdx.x & 7) * 128;
    const int bm = blockIdx.y * 128;
    const int tx = tid & 15;
    const int ty = tid >> 4;

    const float* W    = set ? W1 : W0;
    const float* bias = set ? b1 : b0;
    float*       C    = set ? C1 : C0;

    const int arow = tid >> 1;
    const int acol = (tid & 1) * 4;
    const int brow = tid >> 5;
    const int bcol = (tid & 31) * 4;

    const float* Ap = A + (size_t)(bm + arow) * K + acol;
    const float* Wp = W + (size_t)brow * N + bn + bcol;

    u64 acc[8][4];
    #pragma unroll
    for (int i = 0; i < 8; i++)
        #pragma unroll
        for (int j = 0; j < 4; j++) acc[i][j] = 0ull;

    // prologue: stage 0 into buffer 0
    {
        float4 a4 = *(const float4*)Ap;
        As[0][acol + 0][arow] = a4.x;
        As[0][acol + 1][arow] = a4.y;
        As[0][acol + 2][arow] = a4.z;
        As[0][acol + 3][arow] = a4.w;
        *(float4*)&Bs[0][brow][bcol] = *(const float4*)Wp;
    }
    __syncthreads();

    const int nst = K >> 3;
    for (int s = 0; s < nst; s++) {
        const int cur = s & 1;
        float4 na, nb;
        const bool more = (s + 1 < nst);
        if (more) {
            na = *(const float4*)(Ap + (s + 1) * 8);
            nb = *(const float4*)(Wp + (size_t)(s + 1) * 8 * N);
        }

        #pragma unroll
        for (int kk = 0; kk < 8; kk++) {
            float4 a0 = *(const float4*)&As[cur][kk][ty * 8];
            float4 a1 = *(const float4*)&As[cur][kk][ty * 8 + 4];
            alignas(16) u64 b2[4];
            *(float4*)&b2[0] = *(const float4*)&Bs[cur][kk][tx * 4];
            *(float4*)&b2[2] = *(const float4*)&Bs[cur][kk][64 + tx * 4];
            u64 ad[8];
            ad[0] = pack2(a0.x); ad[1] = pack2(a0.y);
            ad[2] = pack2(a0.z); ad[3] = pack2(a0.w);
            ad[4] = pack2(a1.x); ad[5] = pack2(a1.y);
            ad[6] = pack2(a1.z); ad[7] = pack2(a1.w);
            #pragma unroll
            for (int i = 0; i < 8; i++)
                #pragma unroll
                for (int j = 0; j < 4; j++)
                    ffma2(acc[i][j], ad[i], b2[j]);
        }

        if (more) {
            const int nxt = cur ^ 1;
            As[nxt][acol + 0][arow] = na.x;
            As[nxt][acol + 1][arow] = na.y;
            As[nxt][acol + 2][arow] = na.z;
            As[nxt][acol + 3][arow] = na.w;
            *(float4*)&Bs[nxt][brow][bcol] = nb;
            __syncthreads();
        }
    }

    float4 bb0 = *(const float4*)(bias + bn + tx * 4);
    float4 bb1 = *(const float4*)(bias + bn + 64 + tx * 4);

    #pragma unroll
    for (int i = 0; i < 8; i++) {
        float* Cp = C + (size_t)(bm + ty * 8 + i) * N + bn;
        float2 p0 = unpack2(acc[i][0]), p1 = unpack2(acc[i][1]);
        float2 p2 = unpack2(acc[i][2]), p3 = unpack2(acc[i][3]);
        float4 o0 = make_float4(p0.x + bb0.x, p0.y + bb0.y, p1.x + bb0.z, p1.y + bb0.w);
        float4 o1 = make_float4(p2.x + bb1.x, p2.y + bb1.y, p3.x + bb1.z, p3.y + bb1.w);
        *(float4*)(Cp + tx * 4) = o0;
        *(float4*)(Cp + 64 + tx * 4) = o1;
    }
}

// ---------------------------------------------------------------------------
// Row norms, pre-scaled by SCALE*log2(e)
// ---------------------------------------------------------------------------
__global__ __launch_bounds__(256) void compute_norms(
    const float* __restrict__ q, float* __restrict__ norms)
{
    int idx = blockIdx.x * 256 + threadIdx.x;
    int n  = idx & (NTOK - 1);
    int bh = idx >> 11;
    int h = bh & (HEADS - 1);
    int b = bh >> 4;
    const float* p = q + ((size_t)(b * NTOK + n)) * INNER + h * DH;
    float s = 0.f;
    #pragma unroll
    for (int d = 0; d < DH; d += 4) {
        float4 t = *(const float4*)(p + d);
        s += t.x * t.x + t.y * t.y + t.z * t.z + t.w * t.w;
    }
    norms[idx] = s * CLOG2E;
}

// ---------------------------------------------------------------------------
// Flash attention (k=q), f32x2, no online softmax (R9-proven).
// 3 barriers per j-tile (the pre-Pstore barrier was redundant: Ps is a
// dedicated buffer; previous-tile PV reads are fenced by the top barrier).
// ---------------------------------------------------------------------------
#define QSTR 132
#define KSTR 68
#define VSTR 68
#define PSTR 132

__global__ __launch_bounds__(256) void attn_kernel(
    const float* __restrict__ q, const float* __restrict__ v,
    const float* __restrict__ norms, float* __restrict__ ao)
{
    extern __shared__ float sm[];
    float* Qs = sm;
    float* Ks = Qs + 64 * QSTR;
    float* Vs = Ks + 64 * KSTR;
    float* Ps = Vs + 64 * VSTR;
    float* kn = Ps + 64 * PSTR;

    const int tid = threadIdx.x;
    const int tx = tid & 15;
    const int ty = tid >> 4;
    const int i0 = blockIdx.x * 128;
    const int bh = blockIdx.y;
    const int h = bh & (HEADS - 1);
    const int b = bh >> 4;

    const float* qb = q + (size_t)b * NTOK * INNER + h * DH;
    const float* vb = v + (size_t)b * NTOK * INNER + h * DH;
    const float* nb = norms + (size_t)bh * NTOK;

    #pragma unroll
    for (int it = 0; it < 8; it++) {
        int idx = tid + it * 256;
        int r = idx >> 4;
        int d = (idx & 15) * 4;
        float4 t = *(const float4*)(qb + (size_t)(i0 + r) * INNER + d);
        Qs[(d + 0) * QSTR + r] = t.x;
        Qs[(d + 1) * QSTR + r] = t.y;
        Qs[(d + 2) * QSTR + r] = t.z;
        Qs[(d + 3) * QSTR + r] = t.w;
    }

    float aaC[8], lsum[8];
    #pragma unroll
    for (int r = 0; r < 8; r++) {
        aaC[r] = __ldg(nb + i0 + ty * 8 + r);
        lsum[r] = 0.f;
    }

    u64 acco[4][4];
    #pragma unroll
    for (int ip = 0; ip < 4; ip++)
        #pragma unroll
        for (int c = 0; c < 4; c++) acco[ip][c] = 0ull;

    for (int j0 = 0; j0 < NTOK; j0 += 64) {
        __syncthreads();   // prev-tile PV reads (Ks/Vs/Ps) done; Q store fenced

        #pragma unroll
        for (int it = 0; it < 4; it++) {
            int idx = tid + it * 256;
            int r = idx >> 4;
            int d = (idx & 15) * 4;
            float4 kt = *(const float4*)(qb + (size_t)(j0 + r) * INNER + d);
            Ks[(d + 0) * KSTR + r] = kt.x;
            Ks[(d + 1) * KSTR + r] = kt.y;
            Ks[(d + 2) * KSTR + r] = kt.z;
            Ks[(d + 3) * KSTR + r] = kt.w;
            float4 vt = *(const float4*)(vb + (size_t)(j0 + r) * INNER + d);
            *(float4*)&Vs[r * VSTR + d] = vt;
        }
        if (tid < 64) kn[tid] = nb[j0 + tid];
        __syncthreads();

        u64 accs[4][4];
        #pragma unroll
        for (int ip = 0; ip < 4; ip++)
            #pragma unroll
            for (int c = 0; c < 4; c++) accs[ip][c] = 0ull;

        #pragma unroll 4
        for (int kk = 0; kk < 64; kk++) {
            alignas(16) u64 a2[4];
            *(float4*)&a2[0] = *(const float4*)&Qs[kk * QSTR + ty * 8];
            *(float4*)&a2[2] = *(const float4*)&Qs[kk * QSTR + ty * 8 + 4];
            float4 kv = *(const float4*)&Ks[kk * KSTR + tx * 4];
            u64 b2[4];
            b2[0] = pack2(kv.x); b2[1] = pack2(kv.y);
            b2[2] = pack2(kv.z); b2[3] = pack2(kv.w);
            #pragma unroll
            for (int ip = 0; ip < 4; ip++)
                #pragma unroll
                for (int c = 0; c < 4; c++)
                    ffma2(accs[ip][c], a2[ip], b2[c]);
        }

        float bbC[4];
        #pragma unroll
        for (int c = 0; c < 4; c++) bbC[c] = kn[tx * 4 + c];

        float p[8][4];
        #pragma unroll
        for (int ip = 0; ip < 4; ip++) {
            const float a0 = aaC[2 * ip], a1 = aaC[2 * ip + 1];
            #pragma unroll
            for (int c = 0; c < 4; c++) {
                float2 t = unpack2(accs[ip][c]);
                float p0 = exp2f(fmaf(t.x, TWO_C, -a0) - bbC[c]);
                float p1 = exp2f(fmaf(t.y, TWO_C, -a1) - bbC[c]);
                p[2 * ip][c] = p0;
                p[2 * ip + 1][c] = p1;
                lsum[2 * ip] += p0;
                lsum[2 * ip + 1] += p1;
            }
        }

        // store P (j-major, i contiguous) — no barrier needed before this:
        // Ps is private to this tile phase; previous PV fenced at loop top.
        #pragma unroll
        for (int c = 0; c < 4; c++) {
            int j = tx * 4 + c;
            float4 p0 = make_float4(p[0][c], p[1][c], p[2][c], p[3][c]);
            float4 p1 = make_float4(p[4][c], p[5][c], p[6][c], p[7][c]);
            *(float4*)&Ps[j * PSTR + ty * 8] = p0;
            *(float4*)&Ps[j * PSTR + ty * 8 + 4] = p1;
        }
        __syncthreads();

        #pragma unroll 2
        for (int j = 0; j < 64; j++) {
            alignas(16) u64 p2[4];
            *(float4*)&p2[0] = *(const float4*)&Ps[j * PSTR + ty * 8];
            *(float4*)&p2[2] = *(const float4*)&Ps[j * PSTR + ty * 8 + 4];
            float4 vv = *(const float4*)&Vs[j * VSTR + tx * 4];
            u64 v2[4];
            v2[0] = pack2(vv.x); v2[1] = pack2(vv.y);
            v2[2] = pack2(vv.z); v2[3] = pack2(vv.w);
            #pragma unroll
            for (int ip = 0; ip < 4; ip++)
                #pragma unroll
                for (int c = 0; c < 4; c++)
                    ffma2(acco[ip][c], p2[ip], v2[c]);
        }
    }

    float inv[8];
    #pragma unroll
    for (int r = 0; r < 8; r++) {
        float lv = lsum[r];
        #pragma unroll
        for (int off = 8; off > 0; off >>= 1)
            lv += __shfl_xor_sync(0xffffffffu, lv, off);
        inv[r] = 1.f / lv;
    }

    float* ob = ao + ((size_t)b * NTOK + i0) * INNER + h * DH;
    #pragma unroll
    for (int ip = 0; ip < 4; ip++) {
        float2 o0 = unpack2(acco[ip][0]);
        float2 o1 = unpack2(acco[ip][1]);
        float2 o2 = unpack2(acco[ip][2]);
        float2 o3 = unpack2(acco[ip][3]);
        int r0 = ty * 8 + 2 * ip;
        float inv0 = inv[2 * ip];
        float inv1 = inv[2 * ip + 1];
        float4 w0 = make_float4(o0.x * inv0, o1.x * inv0, o2.x * inv0, o3.x * inv0);
        float4 w1 = make_float4(o0.y * inv1, o1.y * inv1, o2.y * inv1, o3.y * inv1);
        *(float4*)(ob + (size_t)r0 * INNER + tx * 4) = w0;
        *(float4*)(ob + (size_t)(r0 + 1) * INNER + tx * 4) = w1;
    }
}

// ---------------------------------------------------------------------------
extern "C" void kernel_launch(void* const* d_in, const int* in_sizes, int n_in,
                              void* d_out, int out_size)
{
    const float* x  = (const float*)d_in[0];
    const float* Wq = (const float*)d_in[1];
    const float* bq = (const float*)d_in[2];
    const float* Wv = (const float*)d_in[3];
    const float* bv = (const float*)d_in[4];
    const float* Wo = (const float*)d_in[5];
    const float* bo = (const float*)d_in[6];
    float* out = (float*)d_out;

    float *qp, *vp, *aop, *np;
    cudaGetSymbolAddress((void**)&qp,  g_q);
    cudaGetSymbolAddress((void**)&vp,  g_v);
    cudaGetSymbolAddress((void**)&aop, g_ao);
    cudaGetSymbolAddress((void**)&np,  g_norm);

    const int M = BATCH * NTOK;   // 8192

    // fused q+v projection: blocks 0..7 -> Wq/q, 8..15 -> Wv/v
    sgemm_dual<<<dim3(16, M / 128), 256>>>(
        x, Wq, bq, qp, Wv, bv, vp, M, INNER, DMODEL);

    compute_norms<<<(BATCH * HEADS * NTOK) / 256, 256>>>(qp, np);

    int smem = (64 * QSTR + 64 * KSTR + 64 * VSTR + 64 * PSTR + 64) * (int)sizeof(float);
    cudaFuncSetAttribute(attn_kernel,
                         cudaFuncAttributeMaxDynamicSharedMemorySize, smem);
    attn_kernel<<<dim3(NTOK / 128, BATCH * HEADS), 256, smem>>>(qp, vp, np, aop);

    // output projection (single set: both slots point at Wo)
    sgemm_dual<<<dim3(8, M / 128), 256>>>(
        aop, Wo, bo, out, Wo, bo, out, M, DMODEL, INNER);
}

// round 13
// speedup vs baseline: 1.0874x; 1.0043x over previous
#include <cuda_runtime.h>
#include <math.h>
#include <stdint.h>

#define BATCH 4
#define NTOK  2048
#define DMODEL 1024
#define HEADS 16
#define DH    64
#define INNER 1024
#define SCALE 0.125f                 /* 64^-0.5 */
#define CLOG2E 0.1803368801111f      /* SCALE * log2(e) */
#define TWO_C  0.3606737602222f      /* 2 * SCALE * log2(e) */

typedef unsigned long long u64;

__device__ __forceinline__ u64 pack2(float x) {
    u64 r; asm("mov.b64 %0, {%1, %1};" : "=l"(r) : "f"(x)); return r;
}
__device__ __forceinline__ float2 unpack2(u64 a) {
    float2 f; asm("mov.b64 {%0, %1}, %2;" : "=f"(f.x), "=f"(f.y) : "l"(a)); return f;
}
__device__ __forceinline__ void ffma2(u64 &d, u64 a, u64 b) {
    asm("fma.rn.f32x2 %0, %1, %2, %0;" : "+l"(d) : "l"(a), "l"(b));
}
__device__ __forceinline__ uint32_t smem_u32(const void* p) {
    uint32_t a;
    asm("{ .reg .u64 t; cvta.to.shared.u64 t, %1; cvt.u32.u64 %0, t; }"
        : "=r"(a) : "l"(p));
    return a;
}
__device__ __forceinline__ void cp_async16(uint32_t dst, const void* src) {
    asm volatile("cp.async.cg.shared.global [%0], [%1], 16;"
                 :: "r"(dst), "l"(src) : "memory");
}
__device__ __forceinline__ void cp_commit() {
    asm volatile("cp.async.commit_group;" ::: "memory");
}
__device__ __forceinline__ void cp_wait0() {
    asm volatile("cp.async.wait_group 0;" ::: "memory");
}

// Scratch (allocation-free rule: __device__ globals)
__device__ float g_q[BATCH * NTOK * INNER];
__device__ float g_v[BATCH * NTOK * INNER];
__device__ float g_ao[BATCH * NTOK * INNER];
__device__ float g_norm[BATCH * HEADS * NTOK];   // ‖q‖² * SCALE * log2e

// ---------------------------------------------------------------------------
// SGEMM (f32x2, BK=16, cp.async B, double-buffered, dual-output).
// Fragment mapping and k-order identical to the R12-proven kernel; only the
// staging (chunk size + B transfer path) changes.
// ---------------------------------------------------------------------------
#define BK 16

__global__ __launch_bounds__(256, 2) void sgemm_dual(
    const float* __restrict__ A,
    const float* __restrict__ W0, const float* __restrict__ b0, float* __restrict__ C0,
    const float* __restrict__ W1, const float* __restrict__ b1, float* __restrict__ C1,
    int M, int N, int K)
{
    __shared__ float As[2][BK][128];   // [stage][k][m] transposed
    __shared__ float Bs[2][BK][128];   // [stage][k][n]

    const int tid = threadIdx.x;
    const int set = blockIdx.x >> 3;
    const int bn = (blockIdx.x & 7) * 128;
    const int bm = blockIdx.y * 128;
    const int tx = tid & 15;
    const int ty = tid >> 4;

    const float* W    = set ? W1 : W0;
    const float* bias = set ? b1 : b0;
    float*       C    = set ? C1 : C0;

    // A: 2 float4 per thread per stage, same row, cols akq and akq+4
    const int am  = tid >> 1;
    const int akq = (tid & 1) * 8;
    const float* Ap = A + (size_t)(bm + am) * K + akq;

    // B: one row per thread (16 rows), 8 floats at bc, bc+4
    const int br = tid >> 4;
    const int bc = (tid & 15) * 8;
    const float* Wp = W + (size_t)br * N + bn + bc;

    u64 acc[8][4];
    #pragma unroll
    for (int i = 0; i < 8; i++)
        #pragma unroll
        for (int j = 0; j < 4; j++) acc[i][j] = 0ull;

    // prologue: stage 0 into buffer 0
    {
        cp_async16(smem_u32(&Bs[0][br][bc]), Wp);
        cp_async16(smem_u32(&Bs[0][br][bc + 4]), Wp + 4);
        cp_commit();
        float4 a0 = *(const float4*)Ap;
        float4 a1 = *(const float4*)(Ap + 4);
        As[0][akq + 0][am] = a0.x;
        As[0][akq + 1][am] = a0.y;
        As[0][akq + 2][am] = a0.z;
        As[0][akq + 3][am] = a0.w;
        As[0][akq + 4][am] = a1.x;
        As[0][akq + 5][am] = a1.y;
        As[0][akq + 6][am] = a1.z;
        As[0][akq + 7][am] = a1.w;
    }
    cp_wait0();
    __syncthreads();

    const int nst = K / BK;   // 64
    for (int s = 0; s < nst; s++) {
        const int cur = s & 1;
        const bool more = (s + 1 < nst);
        float4 apf0, apf1;
        if (more) {
            const float* Wn = Wp + (size_t)(s + 1) * BK * N;
            cp_async16(smem_u32(&Bs[cur ^ 1][br][bc]), Wn);
            cp_async16(smem_u32(&Bs[cur ^ 1][br][bc + 4]), Wn + 4);
            cp_commit();
            apf0 = *(const float4*)(Ap + (s + 1) * BK);
            apf1 = *(const float4*)(Ap + (s + 1) * BK + 4);
        }

        #pragma unroll
        for (int kk = 0; kk < BK; kk++) {
            float4 a0 = *(const float4*)&As[cur][kk][ty * 8];
            float4 a1 = *(const float4*)&As[cur][kk][ty * 8 + 4];
            alignas(16) u64 b2[4];
            *(float4*)&b2[0] = *(const float4*)&Bs[cur][kk][tx * 4];
            *(float4*)&b2[2] = *(const float4*)&Bs[cur][kk][64 + tx * 4];
            u64 ad[8];
            ad[0] = pack2(a0.x); ad[1] = pack2(a0.y);
            ad[2] = pack2(a0.z); ad[3] = pack2(a0.w);
            ad[4] = pack2(a1.x); ad[5] = pack2(a1.y);
            ad[6] = pack2(a1.z); ad[7] = pack2(a1.w);
            #pragma unroll
            for (int i = 0; i < 8; i++)
                #pragma unroll
                for (int j = 0; j < 4; j++)
                    ffma2(acc[i][j], ad[i], b2[j]);
        }

        if (more) {
            const int nxt = cur ^ 1;
            As[nxt][akq + 0][am] = apf0.x;
            As[nxt][akq + 1][am] = apf0.y;
            As[nxt][akq + 2][am] = apf0.z;
            As[nxt][akq + 3][am] = apf0.w;
            As[nxt][akq + 4][am] = apf1.x;
            As[nxt][akq + 5][am] = apf1.y;
            As[nxt][akq + 6][am] = apf1.z;
            As[nxt][akq + 7][am] = apf1.w;
            cp_wait0();
            __syncthreads();
        }
    }

    float4 bb0 = *(const float4*)(bias + bn + tx * 4);
    float4 bb1 = *(const float4*)(bias + bn + 64 + tx * 4);

    #pragma unroll
    for (int i = 0; i < 8; i++) {
        float* Cp = C + (size_t)(bm + ty * 8 + i) * N + bn;
        float2 p0 = unpack2(acc[i][0]), p1 = unpack2(acc[i][1]);
        float2 p2 = unpack2(acc[i][2]), p3 = unpack2(acc[i][3]);
        float4 o0 = make_float4(p0.x + bb0.x, p0.y + bb0.y, p1.x + bb0.z, p1.y + bb0.w);
        float4 o1 = make_float4(p2.x + bb1.x, p2.y + bb1.y, p3.x + bb1.z, p3.y + bb1.w);
        *(float4*)(Cp + tx * 4) = o0;
        *(float4*)(Cp + 64 + tx * 4) = o1;
    }
}

// ---------------------------------------------------------------------------
// Row norms, pre-scaled by SCALE*log2(e)
// ---------------------------------------------------------------------------
__global__ __launch_bounds__(256) void compute_norms(
    const float* __restrict__ q, float* __restrict__ norms)
{
    int idx = blockIdx.x * 256 + threadIdx.x;
    int n  = idx & (NTOK - 1);
    int bh = idx >> 11;
    int h = bh & (HEADS - 1);
    int b = bh >> 4;
    const float* p = q + ((size_t)(b * NTOK + n)) * INNER + h * DH;
    float s = 0.f;
    #pragma unroll
    for (int d = 0; d < DH; d += 4) {
        float4 t = *(const float4*)(p + d);
        s += t.x * t.x + t.y * t.y + t.z * t.z + t.w * t.w;
    }
    norms[idx] = s * CLOG2E;
}

// ---------------------------------------------------------------------------
// Flash attention (k=q), f32x2, no online softmax.
// P stored at permuted row r(j) = (j&3)*16 + (j>>2)  ->  conflict-free STS
// (per-lane row stride becomes 1 -> full bank-granule spread).
// ---------------------------------------------------------------------------
#define QSTR 132
#define KSTR 68
#define VSTR 68
#define PSTR 132

__global__ __launch_bounds__(256) void attn_kernel(
    const float* __restrict__ q, const float* __restrict__ v,
    const float* __restrict__ norms, float* __restrict__ ao)
{
    extern __shared__ float sm[];
    float* Qs = sm;
    float* Ks = Qs + 64 * QSTR;
    float* Vs = Ks + 64 * KSTR;
    float* Ps = Vs + 64 * VSTR;
    float* kn = Ps + 64 * PSTR;

    const int tid = threadIdx.x;
    const int tx = tid & 15;
    const int ty = tid >> 4;
    const int i0 = blockIdx.x * 128;
    const int bh = blockIdx.y;
    const int h = bh & (HEADS - 1);
    const int b = bh >> 4;

    const float* qb = q + (size_t)b * NTOK * INNER + h * DH;
    const float* vb = v + (size_t)b * NTOK * INNER + h * DH;
    const float* nb = norms + (size_t)bh * NTOK;

    #pragma unroll
    for (int it = 0; it < 8; it++) {
        int idx = tid + it * 256;
        int r = idx >> 4;
        int d = (idx & 15) * 4;
        float4 t = *(const float4*)(qb + (size_t)(i0 + r) * INNER + d);
        Qs[(d + 0) * QSTR + r] = t.x;
        Qs[(d + 1) * QSTR + r] = t.y;
        Qs[(d + 2) * QSTR + r] = t.z;
        Qs[(d + 3) * QSTR + r] = t.w;
    }

    float aaC[8], lsum[8];
    #pragma unroll
    for (int r = 0; r < 8; r++) {
        aaC[r] = __ldg(nb + i0 + ty * 8 + r);
        lsum[r] = 0.f;
    }

    u64 acco[4][4];
    #pragma unroll
    for (int ip = 0; ip < 4; ip++)
        #pragma unroll
        for (int c = 0; c < 4; c++) acco[ip][c] = 0ull;

    for (int j0 = 0; j0 < NTOK; j0 += 64) {
        __syncthreads();   // prev-tile PV reads done; Q store fenced

        #pragma unroll
        for (int it = 0; it < 4; it++) {
            int idx = tid + it * 256;
            int r = idx >> 4;
            int d = (idx & 15) * 4;
            float4 kt = *(const float4*)(qb + (size_t)(j0 + r) * INNER + d);
            Ks[(d + 0) * KSTR + r] = kt.x;
            Ks[(d + 1) * KSTR + r] = kt.y;
            Ks[(d + 2) * KSTR + r] = kt.z;
            Ks[(d + 3) * KSTR + r] = kt.w;
            float4 vt = *(const float4*)(vb + (size_t)(j0 + r) * INNER + d);
            *(float4*)&Vs[r * VSTR + d] = vt;
        }
        if (tid < 64) kn[tid] = nb[j0 + tid];
        __syncthreads();

        u64 accs[4][4];
        #pragma unroll
        for (int ip = 0; ip < 4; ip++)
            #pragma unroll
            for (int c = 0; c < 4; c++) accs[ip][c] = 0ull;

        #pragma unroll 4
        for (int kk = 0; kk < 64; kk++) {
            alignas(16) u64 a2[4];
            *(float4*)&a2[0] = *(const float4*)&Qs[kk * QSTR + ty * 8];
            *(float4*)&a2[2] = *(const float4*)&Qs[kk * QSTR + ty * 8 + 4];
            float4 kv = *(const float4*)&Ks[kk * KSTR + tx * 4];
            u64 b2[4];
            b2[0] = pack2(kv.x); b2[1] = pack2(kv.y);
            b2[2] = pack2(kv.z); b2[3] = pack2(kv.w);
            #pragma unroll
            for (int ip = 0; ip < 4; ip++)
                #pragma unroll
                for (int c = 0; c < 4; c++)
                    ffma2(accs[ip][c], a2[ip], b2[c]);
        }

        float bbC[4];
        #pragma unroll
        for (int c = 0; c < 4; c++) bbC[c] = kn[tx * 4 + c];

        float p[8][4];
        #pragma unroll
        for (int ip = 0; ip < 4; ip++) {
            const float a0 = aaC[2 * ip], a1 = aaC[2 * ip + 1];
            #pragma unroll
            for (int c = 0; c < 4; c++) {
                float2 t = unpack2(accs[ip][c]);
                float p0 = exp2f(fmaf(t.x, TWO_C, -a0) - bbC[c]);
                float p1 = exp2f(fmaf(t.y, TWO_C, -a1) - bbC[c]);
                p[2 * ip][c] = p0;
                p[2 * ip + 1][c] = p1;
                lsum[2 * ip] += p0;
                lsum[2 * ip + 1] += p1;
            }
        }

        // store P at permuted row r(j) = c*16 + tx  (j = tx*4 + c)
        #pragma unroll
        for (int c = 0; c < 4; c++) {
            int r = c * 16 + tx;
            float4 p0 = make_float4(p[0][c], p[1][c], p[2][c], p[3][c]);
            float4 p1 = make_float4(p[4][c], p[5][c], p[6][c], p[7][c]);
            *(float4*)&Ps[r * PSTR + ty * 8] = p0;
            *(float4*)&Ps[r * PSTR + ty * 8 + 4] = p1;
        }
        __syncthreads();

        // PV: iterate permuted rows; true j = t2*4 + c2 for row r = c2*16 + t2
        #pragma unroll 1
        for (int c2 = 0; c2 < 4; c2++) {
            #pragma unroll 4
            for (int t2 = 0; t2 < 16; t2++) {
                int r = c2 * 16 + t2;
                int j = t2 * 4 + c2;
                alignas(16) u64 p2[4];
                *(float4*)&p2[0] = *(const float4*)&Ps[r * PSTR + ty * 8];
                *(float4*)&p2[2] = *(const float4*)&Ps[r * PSTR + ty * 8 + 4];
                float4 vv = *(const float4*)&Vs[j * VSTR + tx * 4];
                u64 v2[4];
                v2[0] = pack2(vv.x); v2[1] = pack2(vv.y);
                v2[2] = pack2(vv.z); v2[3] = pack2(vv.w);
                #pragma unroll
                for (int ip = 0; ip < 4; ip++)
                    #pragma unroll
                    for (int c = 0; c < 4; c++)
                        ffma2(acco[ip][c], p2[ip], v2[c]);
            }
        }
    }

    float inv[8];
    #pragma unroll
    for (int r = 0; r < 8; r++) {
        float lv = lsum[r];
        #pragma unroll
        for (int off = 8; off > 0; off >>= 1)
            lv += __shfl_xor_sync(0xffffffffu, lv, off);
        inv[r] = 1.f / lv;
    }

    float* ob = ao + ((size_t)b * NTOK + i0) * INNER + h * DH;
    #pragma unroll
    for (int ip = 0; ip < 4; ip++) {
        float2 o0 = unpack2(acco[ip][0]);
        float2 o1 = unpack2(acco[ip][1]);
        float2 o2 = unpack2(acco[ip][2]);
        float2 o3 = unpack2(acco[ip][3]);
        int r0 = ty * 8 + 2 * ip;
        float inv0 = inv[2 * ip];
        float inv1 = inv[2 * ip + 1];
        float4 w0 = make_float4(o0.x * inv0, o1.x * inv0, o2.x * inv0, o3.x * inv0);
        float4 w1 = make_float4(o0.y * inv1, o1.y * inv1, o2.y * inv1, o3.y * inv1);
        *(float4*)(ob + (size_t)r0 * INNER + tx * 4) = w0;
        *(float4*)(ob + (size_t)(r0 + 1) * INNER + tx * 4) = w1;
    }
}

// ---------------------------------------------------------------------------
extern "C" void kernel_launch(void* const* d_in, const int* in_sizes, int n_in,
                              void* d_out, int out_size)
{
    const float* x  = (const float*)d_in[0];
    const float* Wq = (const float*)d_in[1];
    const float* bq = (const float*)d_in[2];
    const float* Wv = (const float*)d_in[3];
    const float* bv = (const float*)d_in[4];
    const float* Wo = (const float*)d_in[5];
    const float* bo = (const float*)d_in[6];
    float* out = (float*)d_out;

    float *qp, *vp, *aop, *np;
    cudaGetSymbolAddress((void**)&qp,  g_q);
    cudaGetSymbolAddress((void**)&vp,  g_v);
    cudaGetSymbolAddress((void**)&aop, g_ao);
    cudaGetSymbolAddress((void**)&np,  g_norm);

    const int M = BATCH * NTOK;   // 8192

    // fused q+v projection: blocks 0..7 -> Wq/q, 8..15 -> Wv/v
    sgemm_dual<<<dim3(16, M / 128), 256>>>(
        x, Wq, bq, qp, Wv, bv, vp, M, INNER, DMODEL);

    compute_norms<<<(BATCH * HEADS * NTOK) / 256, 256>>>(qp, np);

    int smem = (64 * QSTR + 64 * KSTR + 64 * VSTR + 64 * PSTR + 64) * (int)sizeof(float);
    cudaFuncSetAttribute(attn_kernel,
                         cudaFuncAttributeMaxDynamicSharedMemorySize, smem);
    attn_kernel<<<dim3(NTOK / 128, BATCH * HEADS), 256, smem>>>(qp, vp, np, aop);

    // output projection (single set: both slots point at Wo)
    sgemm_dual<<<dim3(8, M / 128), 256>>>(
        aop, Wo, bo, out, Wo, bo, out, M, DMODEL, INNER);
}

// round 14
// speedup vs baseline: 1.1316x; 1.0407x over previous
#include <cuda_runtime.h>
#include <math.h>

#define BATCH 4
#define NTOK  2048
#define DMODEL 1024
#define HEADS 16
#define DH    64
#define INNER 1024
#define SCALE 0.125f                 /* 64^-0.5 */
#define CLOG2E 0.1803368801111f      /* SCALE * log2(e) */
#define TWO_C  0.3606737602222f      /* 2 * SCALE * log2(e) */

typedef unsigned long long u64;

__device__ __forceinline__ u64 pack2(float x) {
    u64 r; asm("mov.b64 %0, {%1, %1};" : "=l"(r) : "f"(x)); return r;
}
__device__ __forceinline__ float2 unpack2(u64 a) {
    float2 f; asm("mov.b64 {%0, %1}, %2;" : "=f"(f.x), "=f"(f.y) : "l"(a)); return f;
}
__device__ __forceinline__ void ffma2(u64 &d, u64 a, u64 b) {
    asm("fma.rn.f32x2 %0, %1, %2, %0;" : "+l"(d) : "l"(a), "l"(b));
}

// Scratch (allocation-free rule: __device__ globals)
__device__ float g_q[BATCH * NTOK * INNER];
__device__ float g_v[BATCH * NTOK * INNER];
__device__ float g_ao[BATCH * NTOK * INNER];
__device__ float g_norm[BATCH * HEADS * NTOK];   // ‖q‖² * SCALE * log2e

// ---------------------------------------------------------------------------
// SGEMM (f32x2, BK=8, double-buffered, dual-output) — R12-proven core.
//   set = blockIdx.x >> 3 selects {W0,b0,C0} or {W1,b1,C1} (same A).
// NEW: when nrm != nullptr and set == 0, the epilogue also emits per-row
// per-head squared norms (scaled by CLOG2E) — each 128-col tile holds
// exactly 2 complete heads (DH=64).
// ---------------------------------------------------------------------------
__global__ __launch_bounds__(256, 2) void sgemm_dual(
    const float* __restrict__ A,
    const float* __restrict__ W0, const float* __restrict__ b0, float* __restrict__ C0,
    const float* __restrict__ W1, const float* __restrict__ b1, float* __restrict__ C1,
    float* __restrict__ nrm,
    int M, int N, int K)
{
    __shared__ float As[2][8][128];   // [stage][k][m] transposed
    __shared__ float Bs[2][8][128];   // [stage][k][n]

    const int tid = threadIdx.x;
    const int set = blockIdx.x >> 3;
    const int bn = (blockIdx.x & 7) * 128;
    const int bm = blockIdx.y * 128;
    const int tx = tid & 15;
    const int ty = tid >> 4;

    const float* W    = set ? W1 : W0;
    const float* bias = set ? b1 : b0;
    float*       C    = set ? C1 : C0;

    const int arow = tid >> 1;
    const int acol = (tid & 1) * 4;
    const int brow = tid >> 5;
    const int bcol = (tid & 31) * 4;

    const float* Ap = A + (size_t)(bm + arow) * K + acol;
    const float* Wp = W + (size_t)brow * N + bn + bcol;

    u64 acc[8][4];
    #pragma unroll
    for (int i = 0; i < 8; i++)
        #pragma unroll
        for (int j = 0; j < 4; j++) acc[i][j] = 0ull;

    // prologue: stage 0 into buffer 0
    {
        float4 a4 = *(const float4*)Ap;
        As[0][acol + 0][arow] = a4.x;
        As[0][acol + 1][arow] = a4.y;
        As[0][acol + 2][arow] = a4.z;
        As[0][acol + 3][arow] = a4.w;
        *(float4*)&Bs[0][brow][bcol] = *(const float4*)Wp;
    }
    __syncthreads();

    const int nst = K >> 3;
    for (int s = 0; s < nst; s++) {
        const int cur = s & 1;
        float4 na, nb;
        const bool more = (s + 1 < nst);
        if (more) {
            na = *(const float4*)(Ap + (s + 1) * 8);
            nb = *(const float4*)(Wp + (size_t)(s + 1) * 8 * N);
        }

        #pragma unroll
        for (int kk = 0; kk < 8; kk++) {
            float4 a0 = *(const float4*)&As[cur][kk][ty * 8];
            float4 a1 = *(const float4*)&As[cur][kk][ty * 8 + 4];
            alignas(16) u64 b2[4];
            *(float4*)&b2[0] = *(const float4*)&Bs[cur][kk][tx * 4];
            *(float4*)&b2[2] = *(const float4*)&Bs[cur][kk][64 + tx * 4];
            u64 ad[8];
            ad[0] = pack2(a0.x); ad[1] = pack2(a0.y);
            ad[2] = pack2(a0.z); ad[3] = pack2(a0.w);
            ad[4] = pack2(a1.x); ad[5] = pack2(a1.y);
            ad[6] = pack2(a1.z); ad[7] = pack2(a1.w);
            #pragma unroll
            for (int i = 0; i < 8; i++)
                #pragma unroll
                for (int j = 0; j < 4; j++)
                    ffma2(acc[i][j], ad[i], b2[j]);
        }

        if (more) {
            const int nxt = cur ^ 1;
            As[nxt][acol + 0][arow] = na.x;
            As[nxt][acol + 1][arow] = na.y;
            As[nxt][acol + 2][arow] = na.z;
            As[nxt][acol + 3][arow] = na.w;
            *(float4*)&Bs[nxt][brow][bcol] = nb;
            __syncthreads();
        }
    }

    float4 bb0 = *(const float4*)(bias + bn + tx * 4);
    float4 bb1 = *(const float4*)(bias + bn + 64 + tx * 4);

    float ns0[8], ns1[8];   // per-row squared-norm partials (head0/head1 halves)

    #pragma unroll
    for (int i = 0; i < 8; i++) {
        float* Cp = C + (size_t)(bm + ty * 8 + i) * N + bn;
        float2 p0 = unpack2(acc[i][0]), p1 = unpack2(acc[i][1]);
        float2 p2 = unpack2(acc[i][2]), p3 = unpack2(acc[i][3]);
        float4 o0 = make_float4(p0.x + bb0.x, p0.y + bb0.y, p1.x + bb0.z, p1.y + bb0.w);
        float4 o1 = make_float4(p2.x + bb1.x, p2.y + bb1.y, p3.x + bb1.z, p3.y + bb1.w);
        *(float4*)(Cp + tx * 4) = o0;
        *(float4*)(Cp + 64 + tx * 4) = o1;
        ns0[i] = o0.x * o0.x + o0.y * o0.y + o0.z * o0.z + o0.w * o0.w;
        ns1[i] = o1.x * o1.x + o1.y * o1.y + o1.z * o1.z + o1.w * o1.w;
    }

    // fused per-head norms (q projection only): reduce over the 16 tx lanes
    if (nrm != nullptr && set == 0) {
        #pragma unroll
        for (int i = 0; i < 8; i++) {
            #pragma unroll
            for (int off = 8; off > 0; off >>= 1) {
                ns0[i] += __shfl_xor_sync(0xffffffffu, ns0[i], off);
                ns1[i] += __shfl_xor_sync(0xffffffffu, ns1[i], off);
            }
        }
        if (tx == 0) {
            const int h0 = (blockIdx.x & 7) * 2;
            #pragma unroll
            for (int i = 0; i < 8; i++) {
                int row = bm + ty * 8 + i;          // global row = b*NTOK + n
                int b = row >> 11;
                int n = row & (NTOK - 1);
                nrm[((size_t)(b * HEADS + h0)) * NTOK + n]     = ns0[i] * CLOG2E;
                nrm[((size_t)(b * HEADS + h0 + 1)) * NTOK + n] = ns1[i] * CLOG2E;
            }
        }
    }
}

// ---------------------------------------------------------------------------
// Flash attention (k=q), f32x2, no online softmax; P stored at permuted row
// r(j) = (j&3)*16 + (j>>2) for conflict-free STS (R13-proven).
// ---------------------------------------------------------------------------
#define QSTR 132
#define KSTR 68
#define VSTR 68
#define PSTR 132

__global__ __launch_bounds__(256) void attn_kernel(
    const float* __restrict__ q, const float* __restrict__ v,
    const float* __restrict__ norms, float* __restrict__ ao)
{
    extern __shared__ float sm[];
    float* Qs = sm;
    float* Ks = Qs + 64 * QSTR;
    float* Vs = Ks + 64 * KSTR;
    float* Ps = Vs + 64 * VSTR;
    float* kn = Ps + 64 * PSTR;

    const int tid = threadIdx.x;
    const int tx = tid & 15;
    const int ty = tid >> 4;
    const int i0 = blockIdx.x * 128;
    const int bh = blockIdx.y;
    const int h = bh & (HEADS - 1);
    const int b = bh >> 4;

    const float* qb = q + (size_t)b * NTOK * INNER + h * DH;
    const float* vb = v + (size_t)b * NTOK * INNER + h * DH;
    const float* nb = norms + (size_t)bh * NTOK;

    #pragma unroll
    for (int it = 0; it < 8; it++) {
        int idx = tid + it * 256;
        int r = idx >> 4;
        int d = (idx & 15) * 4;
        float4 t = *(const float4*)(qb + (size_t)(i0 + r) * INNER + d);
        Qs[(d + 0) * QSTR + r] = t.x;
        Qs[(d + 1) * QSTR + r] = t.y;
        Qs[(d + 2) * QSTR + r] = t.z;
        Qs[(d + 3) * QSTR + r] = t.w;
    }

    float aaC[8], lsum[8];
    #pragma unroll
    for (int r = 0; r < 8; r++) {
        aaC[r] = __ldg(nb + i0 + ty * 8 + r);
        lsum[r] = 0.f;
    }

    u64 acco[4][4];
    #pragma unroll
    for (int ip = 0; ip < 4; ip++)
        #pragma unroll
        for (int c = 0; c < 4; c++) acco[ip][c] = 0ull;

    for (int j0 = 0; j0 < NTOK; j0 += 64) {
        __syncthreads();   // prev-tile PV reads done; Q store fenced

        #pragma unroll
        for (int it = 0; it < 4; it++) {
            int idx = tid + it * 256;
            int r = idx >> 4;
            int d = (idx & 15) * 4;
            float4 kt = *(const float4*)(qb + (size_t)(j0 + r) * INNER + d);
            Ks[(d + 0) * KSTR + r] = kt.x;
            Ks[(d + 1) * KSTR + r] = kt.y;
            Ks[(d + 2) * KSTR + r] = kt.z;
            Ks[(d + 3) * KSTR + r] = kt.w;
            float4 vt = *(const float4*)(vb + (size_t)(j0 + r) * INNER + d);
            *(float4*)&Vs[r * VSTR + d] = vt;
        }
        if (tid < 64) kn[tid] = nb[j0 + tid];
        __syncthreads();

        u64 accs[4][4];
        #pragma unroll
        for (int ip = 0; ip < 4; ip++)
            #pragma unroll
            for (int c = 0; c < 4; c++) accs[ip][c] = 0ull;

        #pragma unroll 4
        for (int kk = 0; kk < 64; kk++) {
            alignas(16) u64 a2[4];
            *(float4*)&a2[0] = *(const float4*)&Qs[kk * QSTR + ty * 8];
            *(float4*)&a2[2] = *(const float4*)&Qs[kk * QSTR + ty * 8 + 4];
            float4 kv = *(const float4*)&Ks[kk * KSTR + tx * 4];
            u64 b2[4];
            b2[0] = pack2(kv.x); b2[1] = pack2(kv.y);
            b2[2] = pack2(kv.z); b2[3] = pack2(kv.w);
            #pragma unroll
            for (int ip = 0; ip < 4; ip++)
                #pragma unroll
                for (int c = 0; c < 4; c++)
                    ffma2(accs[ip][c], a2[ip], b2[c]);
        }

        float bbC[4];
        #pragma unroll
        for (int c = 0; c < 4; c++) bbC[c] = kn[tx * 4 + c];

        float p[8][4];
        #pragma unroll
        for (int ip = 0; ip < 4; ip++) {
            const float a0 = aaC[2 * ip], a1 = aaC[2 * ip + 1];
            #pragma unroll
            for (int c = 0; c < 4; c++) {
                float2 t = unpack2(accs[ip][c]);
                float p0 = exp2f(fmaf(t.x, TWO_C, -a0) - bbC[c]);
                float p1 = exp2f(fmaf(t.y, TWO_C, -a1) - bbC[c]);
                p[2 * ip][c] = p0;
                p[2 * ip + 1][c] = p1;
                lsum[2 * ip] += p0;
                lsum[2 * ip + 1] += p1;
            }
        }

        // store P at permuted row r(j) = c*16 + tx  (j = tx*4 + c)
        #pragma unroll
        for (int c = 0; c < 4; c++) {
            int r = c * 16 + tx;
            float4 p0 = make_float4(p[0][c], p[1][c], p[2][c], p[3][c]);
            float4 p1 = make_float4(p[4][c], p[5][c], p[6][c], p[7][c]);
            *(float4*)&Ps[r * PSTR + ty * 8] = p0;
            *(float4*)&Ps[r * PSTR + ty * 8 + 4] = p1;
        }
        __syncthreads();

        // PV: iterate permuted rows; true j = t2*4 + c2 for row r = c2*16 + t2
        #pragma unroll 1
        for (int c2 = 0; c2 < 4; c2++) {
            #pragma unroll 4
            for (int t2 = 0; t2 < 16; t2++) {
                int r = c2 * 16 + t2;
                int j = t2 * 4 + c2;
                alignas(16) u64 p2[4];
                *(float4*)&p2[0] = *(const float4*)&Ps[r * PSTR + ty * 8];
                *(float4*)&p2[2] = *(const float4*)&Ps[r * PSTR + ty * 8 + 4];
                float4 vv = *(const float4*)&Vs[j * VSTR + tx * 4];
                u64 v2[4];
                v2[0] = pack2(vv.x); v2[1] = pack2(vv.y);
                v2[2] = pack2(vv.z); v2[3] = pack2(vv.w);
                #pragma unroll
                for (int ip = 0; ip < 4; ip++)
                    #pragma unroll
                    for (int c = 0; c < 4; c++)
                        ffma2(acco[ip][c], p2[ip], v2[c]);
            }
        }
    }

    float inv[8];
    #pragma unroll
    for (int r = 0; r < 8; r++) {
        float lv = lsum[r];
        #pragma unroll
        for (int off = 8; off > 0; off >>= 1)
            lv += __shfl_xor_sync(0xffffffffu, lv, off);
        inv[r] = 1.f / lv;
    }

    float* ob = ao + ((size_t)b * NTOK + i0) * INNER + h * DH;
    #pragma unroll
    for (int ip = 0; ip < 4; ip++) {
        float2 o0 = unpack2(acco[ip][0]);
        float2 o1 = unpack2(acco[ip][1]);
        float2 o2 = unpack2(acco[ip][2]);
        float2 o3 = unpack2(acco[ip][3]);
        int r0 = ty * 8 + 2 * ip;
        float inv0 = inv[2 * ip];
        float inv1 = inv[2 * ip + 1];
        float4 w0 = make_float4(o0.x * inv0, o1.x * inv0, o2.x * inv0, o3.x * inv0);
        float4 w1 = make_float4(o0.y * inv1, o1.y * inv1, o2.y * inv1, o3.y * inv1);
        *(float4*)(ob + (size_t)r0 * INNER + tx * 4) = w0;
        *(float4*)(ob + (size_t)(r0 + 1) * INNER + tx * 4) = w1;
    }
}

// ---------------------------------------------------------------------------
extern "C" void kernel_launch(void* const* d_in, const int* in_sizes, int n_in,
                              void* d_out, int out_size)
{
    const float* x  = (const float*)d_in[0];
    const float* Wq = (const float*)d_in[1];
    const float* bq = (const float*)d_in[2];
    const float* Wv = (const float*)d_in[3];
    const float* bv = (const float*)d_in[4];
    const float* Wo = (const float*)d_in[5];
    const float* bo = (const float*)d_in[6];
    float* out = (float*)d_out;

    float *qp, *vp, *aop, *np;
    cudaGetSymbolAddress((void**)&qp,  g_q);
    cudaGetSymbolAddress((void**)&vp,  g_v);
    cudaGetSymbolAddress((void**)&aop, g_ao);
    cudaGetSymbolAddress((void**)&np,  g_norm);

    const int M = BATCH * NTOK;   // 8192

    // fused q+v projection (norms fused into q epilogue):
    //   blocks 0..7 -> Wq/q, 8..15 -> Wv/v
    sgemm_dual<<<dim3(16, M / 128), 256>>>(
        x, Wq, bq, qp, Wv, bv, vp, np, M, INNER, DMODEL);

    int smem = (64 * QSTR + 64 * KSTR + 64 * VSTR + 64 * PSTR + 64) * (int)sizeof(float);
    cudaFuncSetAttribute(attn_kernel,
                         cudaFuncAttributeMaxDynamicSharedMemorySize, smem);
    attn_kernel<<<dim3(NTOK / 128, BATCH * HEADS), 256, smem>>>(qp, vp, np, aop);

    // output projection (single set: both slots point at Wo, no norms)
    sgemm_dual<<<dim3(8, M / 128), 256>>>(
        aop, Wo, bo, out, Wo, bo, out, nullptr, M, DMODEL, INNER);
}

// round 15
// speedup vs baseline: 1.1375x; 1.0052x over previous
#include <cuda_runtime.h>
#include <math.h>

#define BATCH 4
#define NTOK  2048
#define DMODEL 1024
#define HEADS 16
#define DH    64
#define INNER 1024
#define SCALE 0.125f                 /* 64^-0.5 */
#define CLOG2E 0.1803368801111f      /* SCALE * log2(e) */
#define TWO_C  0.3606737602222f      /* 2 * SCALE * log2(e) */

typedef unsigned long long u64;

__device__ __forceinline__ u64 pack2(float x) {
    u64 r; asm("mov.b64 %0, {%1, %1};" : "=l"(r) : "f"(x)); return r;
}
__device__ __forceinline__ float2 unpack2(u64 a) {
    float2 f; asm("mov.b64 {%0, %1}, %2;" : "=f"(f.x), "=f"(f.y) : "l"(a)); return f;
}
__device__ __forceinline__ void ffma2(u64 &d, u64 a, u64 b) {
    asm("fma.rn.f32x2 %0, %1, %2, %0;" : "+l"(d) : "l"(a), "l"(b));
}

// Scratch (allocation-free rule: __device__ globals)
__device__ float g_q[BATCH * NTOK * INNER];
__device__ float g_v[BATCH * NTOK * INNER];
__device__ float g_ao[BATCH * NTOK * INNER];
__device__ float g_norm[BATCH * HEADS * NTOK];   // ‖q‖² * SCALE * log2e

// ---------------------------------------------------------------------------
// SGEMM (f32x2, BK=8, double-buffered, dual-output) — R14-proven, unchanged.
// ---------------------------------------------------------------------------
__global__ __launch_bounds__(256, 2) void sgemm_dual(
    const float* __restrict__ A,
    const float* __restrict__ W0, const float* __restrict__ b0, float* __restrict__ C0,
    const float* __restrict__ W1, const float* __restrict__ b1, float* __restrict__ C1,
    float* __restrict__ nrm,
    int M, int N, int K)
{
    __shared__ float As[2][8][128];
    __shared__ float Bs[2][8][128];

    const int tid = threadIdx.x;
    const int set = blockIdx.x >> 3;
    const int bn = (blockIdx.x & 7) * 128;
    const int bm = blockIdx.y * 128;
    const int tx = tid & 15;
    const int ty = tid >> 4;

    const float* W    = set ? W1 : W0;
    const float* bias = set ? b1 : b0;
    float*       C    = set ? C1 : C0;

    const int arow = tid >> 1;
    const int acol = (tid & 1) * 4;
    const int brow = tid >> 5;
    const int bcol = (tid & 31) * 4;

    const float* Ap = A + (size_t)(bm + arow) * K + acol;
    const float* Wp = W + (size_t)brow * N + bn + bcol;

    u64 acc[8][4];
    #pragma unroll
    for (int i = 0; i < 8; i++)
        #pragma unroll
        for (int j = 0; j < 4; j++) acc[i][j] = 0ull;

    {
        float4 a4 = *(const float4*)Ap;
        As[0][acol + 0][arow] = a4.x;
        As[0][acol + 1][arow] = a4.y;
        As[0][acol + 2][arow] = a4.z;
        As[0][acol + 3][arow] = a4.w;
        *(float4*)&Bs[0][brow][bcol] = *(const float4*)Wp;
    }
    __syncthreads();

    const int nst = K >> 3;
    for (int s = 0; s < nst; s++) {
        const int cur = s & 1;
        float4 na, nb;
        const bool more = (s + 1 < nst);
        if (more) {
            na = *(const float4*)(Ap + (s + 1) * 8);
            nb = *(const float4*)(Wp + (size_t)(s + 1) * 8 * N);
        }

        #pragma unroll
        for (int kk = 0; kk < 8; kk++) {
            float4 a0 = *(const float4*)&As[cur][kk][ty * 8];
            float4 a1 = *(const float4*)&As[cur][kk][ty * 8 + 4];
            alignas(16) u64 b2[4];
            *(float4*)&b2[0] = *(const float4*)&Bs[cur][kk][tx * 4];
            *(float4*)&b2[2] = *(const float4*)&Bs[cur][kk][64 + tx * 4];
            u64 ad[8];
            ad[0] = pack2(a0.x); ad[1] = pack2(a0.y);
            ad[2] = pack2(a0.z); ad[3] = pack2(a0.w);
            ad[4] = pack2(a1.x); ad[5] = pack2(a1.y);
            ad[6] = pack2(a1.z); ad[7] = pack2(a1.w);
            #pragma unroll
            for (int i = 0; i < 8; i++)
                #pragma unroll
                for (int j = 0; j < 4; j++)
                    ffma2(acc[i][j], ad[i], b2[j]);
        }

        if (more) {
            const int nxt = cur ^ 1;
            As[nxt][acol + 0][arow] = na.x;
            As[nxt][acol + 1][arow] = na.y;
            As[nxt][acol + 2][arow] = na.z;
            As[nxt][acol + 3][arow] = na.w;
            *(float4*)&Bs[nxt][brow][bcol] = nb;
            __syncthreads();
        }
    }

    float4 bb0 = *(const float4*)(bias + bn + tx * 4);
    float4 bb1 = *(const float4*)(bias + bn + 64 + tx * 4);

    float ns0[8], ns1[8];

    #pragma unroll
    for (int i = 0; i < 8; i++) {
        float* Cp = C + (size_t)(bm + ty * 8 + i) * N + bn;
        float2 p0 = unpack2(acc[i][0]), p1 = unpack2(acc[i][1]);
        float2 p2 = unpack2(acc[i][2]), p3 = unpack2(acc[i][3]);
        float4 o0 = make_float4(p0.x + bb0.x, p0.y + bb0.y, p1.x + bb0.z, p1.y + bb0.w);
        float4 o1 = make_float4(p2.x + bb1.x, p2.y + bb1.y, p3.x + bb1.z, p3.y + bb1.w);
        *(float4*)(Cp + tx * 4) = o0;
        *(float4*)(Cp + 64 + tx * 4) = o1;
        ns0[i] = o0.x * o0.x + o0.y * o0.y + o0.z * o0.z + o0.w * o0.w;
        ns1[i] = o1.x * o1.x + o1.y * o1.y + o1.z * o1.z + o1.w * o1.w;
    }

    if (nrm != nullptr && set == 0) {
        #pragma unroll
        for (int i = 0; i < 8; i++) {
            #pragma unroll
            for (int off = 8; off > 0; off >>= 1) {
                ns0[i] += __shfl_xor_sync(0xffffffffu, ns0[i], off);
                ns1[i] += __shfl_xor_sync(0xffffffffu, ns1[i], off);
            }
        }
        if (tx == 0) {
            const int h0 = (blockIdx.x & 7) * 2;
            #pragma unroll
            for (int i = 0; i < 8; i++) {
                int row = bm + ty * 8 + i;
                int b = row >> 11;
                int n = row & (NTOK - 1);
                nrm[((size_t)(b * HEADS + h0)) * NTOK + n]     = ns0[i] * CLOG2E;
                nrm[((size_t)(b * HEADS + h0 + 1)) * NTOK + n] = ns1[i] * CLOG2E;
            }
        }
    }
}

// ---------------------------------------------------------------------------
// Flash attention (k=q), f32x2, no online softmax.
// NEW shape: 128 threads (16 ty x 8 tx), per-thread 8i x 8j  => 1.0 B/MAC
// (crossbar demand balanced against FFMA2 demand).
// P stored at permuted row r(j) = (j&7)*8 + (j>>3)  (j = tx*8 + c -> r = c*8+tx)
// ---------------------------------------------------------------------------
#define QSTR 132
#define KSTR 68
#define VSTR 68
#define PSTR 132

__global__ __launch_bounds__(128, 2) void attn_kernel(
    const float* __restrict__ q, const float* __restrict__ v,
    const float* __restrict__ norms, float* __restrict__ ao)
{
    extern __shared__ float sm[];
    float* Qs = sm;                   // [64 d][132]  (128 i used)
    float* Ks = Qs + 64 * QSTR;       // [64 d][68]   (64 j used)
    float* Vs = Ks + 64 * KSTR;       // [64 j][68]   (64 d used)
    float* Ps = Vs + 64 * VSTR;       // [64 r][132]  (128 i used)
    float* kn = Ps + 64 * PSTR;       // [64]

    const int tid = threadIdx.x;
    const int tx = tid & 7;           // j-group (8 cols x 8)
    const int ty = tid >> 3;          // i-group (16 rows x 8)
    const int i0 = blockIdx.x * 128;
    const int bh = blockIdx.y;
    const int h = bh & (HEADS - 1);
    const int b = bh >> 4;

    const float* qb = q + (size_t)b * NTOK * INNER + h * DH;
    const float* vb = v + (size_t)b * NTOK * INNER + h * DH;
    const float* nb = norms + (size_t)bh * NTOK;

    // Q tile transposed: Qs[d][i], 128 rows x 64 d  (2048 float4, 16 iters)
    #pragma unroll
    for (int it = 0; it < 16; it++) {
        int idx = tid + it * 128;
        int r = idx >> 4;
        int d = (idx & 15) * 4;
        float4 t = *(const float4*)(qb + (size_t)(i0 + r) * INNER + d);
        Qs[(d + 0) * QSTR + r] = t.x;
        Qs[(d + 1) * QSTR + r] = t.y;
        Qs[(d + 2) * QSTR + r] = t.z;
        Qs[(d + 3) * QSTR + r] = t.w;
    }

    float aaC[8], lsum[8];
    #pragma unroll
    for (int r = 0; r < 8; r++) {
        aaC[r] = __ldg(nb + i0 + ty * 8 + r);
        lsum[r] = 0.f;
    }

    u64 acco[4][8];                   // [i-pair][c]
    #pragma unroll
    for (int ip = 0; ip < 4; ip++)
        #pragma unroll
        for (int c = 0; c < 8; c++) acco[ip][c] = 0ull;

    for (int j0 = 0; j0 < NTOK; j0 += 64) {
        __syncthreads();   // prev-tile PV reads done; Q store fenced

        // K transposed + V natural (64 rows x 16 float4 each, 8 iters each)
        #pragma unroll
        for (int it = 0; it < 8; it++) {
            int idx = tid + it * 128;
            int r = idx >> 4;
            int d = (idx & 15) * 4;
            float4 kt = *(const float4*)(qb + (size_t)(j0 + r) * INNER + d);
            Ks[(d + 0) * KSTR + r] = kt.x;
            Ks[(d + 1) * KSTR + r] = kt.y;
            Ks[(d + 2) * KSTR + r] = kt.z;
            Ks[(d + 3) * KSTR + r] = kt.w;
            float4 vt = *(const float4*)(vb + (size_t)(j0 + r) * INNER + d);
            *(float4*)&Vs[r * VSTR + d] = vt;
        }
        if (tid < 64) kn[tid] = nb[j0 + tid];
        __syncthreads();

        // ---- S = Q @ K^T : per-thread 8i(4 pairs) x 8j ----
        u64 accs[4][8];
        #pragma unroll
        for (int ip = 0; ip < 4; ip++)
            #pragma unroll
            for (int c = 0; c < 8; c++) accs[ip][c] = 0ull;

        #pragma unroll 4
        for (int kk = 0; kk < 64; kk++) {
            alignas(16) u64 a2[4];
            *(float4*)&a2[0] = *(const float4*)&Qs[kk * QSTR + ty * 8];
            *(float4*)&a2[2] = *(const float4*)&Qs[kk * QSTR + ty * 8 + 4];
            float4 k0 = *(const float4*)&Ks[kk * KSTR + tx * 8];
            float4 k1 = *(const float4*)&Ks[kk * KSTR + tx * 8 + 4];
            u64 b2[8];
            b2[0] = pack2(k0.x); b2[1] = pack2(k0.y);
            b2[2] = pack2(k0.z); b2[3] = pack2(k0.w);
            b2[4] = pack2(k1.x); b2[5] = pack2(k1.y);
            b2[6] = pack2(k1.z); b2[7] = pack2(k1.w);
            #pragma unroll
            for (int ip = 0; ip < 4; ip++)
                #pragma unroll
                for (int c = 0; c < 8; c++)
                    ffma2(accs[ip][c], a2[ip], b2[c]);
        }

        // ---- p = exp2(qk*2C - aaC - bbC); plain l accumulation ----
        float bbC[8];
        #pragma unroll
        for (int c = 0; c < 8; c++) bbC[c] = kn[tx * 8 + c];

        float p[8][8];
        #pragma unroll
        for (int ip = 0; ip < 4; ip++) {
            const float a0 = aaC[2 * ip], a1 = aaC[2 * ip + 1];
            #pragma unroll
            for (int c = 0; c < 8; c++) {
                float2 t = unpack2(accs[ip][c]);
                float p0 = exp2f(fmaf(t.x, TWO_C, -a0) - bbC[c]);
                float p1 = exp2f(fmaf(t.y, TWO_C, -a1) - bbC[c]);
                p[2 * ip][c] = p0;
                p[2 * ip + 1][c] = p1;
                lsum[2 * ip] += p0;
                lsum[2 * ip + 1] += p1;
            }
        }

        // store P at permuted row r = c*8 + tx  (j = tx*8 + c)
        #pragma unroll
        for (int c = 0; c < 8; c++) {
            int r = c * 8 + tx;
            float4 p0 = make_float4(p[0][c], p[1][c], p[2][c], p[3][c]);
            float4 p1 = make_float4(p[4][c], p[5][c], p[6][c], p[7][c]);
            *(float4*)&Ps[r * PSTR + ty * 8] = p0;
            *(float4*)&Ps[r * PSTR + ty * 8 + 4] = p1;
        }
        __syncthreads();

        // ---- PV: iterate permuted rows; r = c2*8 + t2 holds j = t2*8 + c2 ----
        #pragma unroll 1
        for (int c2 = 0; c2 < 8; c2++) {
            #pragma unroll 4
            for (int t2 = 0; t2 < 8; t2++) {
                int r = c2 * 8 + t2;
                int j = t2 * 8 + c2;
                alignas(16) u64 p2[4];
                *(float4*)&p2[0] = *(const float4*)&Ps[r * PSTR + ty * 8];
                *(float4*)&p2[2] = *(const float4*)&Ps[r * PSTR + ty * 8 + 4];
                float4 v0 = *(const float4*)&Vs[j * VSTR + tx * 8];
                float4 v1 = *(const float4*)&Vs[j * VSTR + tx * 8 + 4];
                u64 v2[8];
                v2[0] = pack2(v0.x); v2[1] = pack2(v0.y);
                v2[2] = pack2(v0.z); v2[3] = pack2(v0.w);
                v2[4] = pack2(v1.x); v2[5] = pack2(v1.y);
                v2[6] = pack2(v1.z); v2[7] = pack2(v1.w);
                #pragma unroll
                for (int ip = 0; ip < 4; ip++)
                    #pragma unroll
                    for (int c = 0; c < 8; c++)
                        ffma2(acco[ip][c], p2[ip], v2[c]);
            }
        }
    }

    // final l reduction over the 8 tx lanes
    float inv[8];
    #pragma unroll
    for (int r = 0; r < 8; r++) {
        float lv = lsum[r];
        #pragma unroll
        for (int off = 4; off > 0; off >>= 1)
            lv += __shfl_xor_sync(0xffffffffu, lv, off);
        inv[r] = 1.f / lv;
    }

    // epilogue: rows ty*8 + 2ip + {0,1}, cols tx*8 .. +7
    float* ob = ao + ((size_t)b * NTOK + i0) * INNER + h * DH;
    #pragma unroll
    for (int ip = 0; ip < 4; ip++) {
        float2 o[8];
        #pragma unroll
        for (int c = 0; c < 8; c++) o[c] = unpack2(acco[ip][c]);
        int r0 = ty * 8 + 2 * ip;
        float inv0 = inv[2 * ip];
        float inv1 = inv[2 * ip + 1];
        float4 w00 = make_float4(o[0].x * inv0, o[1].x * inv0, o[2].x * inv0, o[3].x * inv0);
        float4 w01 = make_float4(o[4].x * inv0, o[5].x * inv0, o[6].x * inv0, o[7].x * inv0);
        float4 w10 = make_float4(o[0].y * inv1, o[1].y * inv1, o[2].y * inv1, o[3].y * inv1);
        float4 w11 = make_float4(o[4].y * inv1, o[5].y * inv1, o[6].y * inv1, o[7].y * inv1);
        *(float4*)(ob + (size_t)r0 * INNER + tx * 8) = w00;
        *(float4*)(ob + (size_t)r0 * INNER + tx * 8 + 4) = w01;
        *(float4*)(ob + (size_t)(r0 + 1) * INNER + tx * 8) = w10;
        *(float4*)(ob + (size_t)(r0 + 1) * INNER + tx * 8 + 4) = w11;
    }
}

// ---------------------------------------------------------------------------
extern "C" void kernel_launch(void* const* d_in, const int* in_sizes, int n_in,
                              void* d_out, int out_size)
{
    const float* x  = (const float*)d_in[0];
    const float* Wq = (const float*)d_in[1];
    const float* bq = (const float*)d_in[2];
    const float* Wv = (const float*)d_in[3];
    const float* bv = (const float*)d_in[4];
    const float* Wo = (const float*)d_in[5];
    const float* bo = (const float*)d_in[6];
    float* out = (float*)d_out;

    float *qp, *vp, *aop, *np;
    cudaGetSymbolAddress((void**)&qp,  g_q);
    cudaGetSymbolAddress((void**)&vp,  g_v);
    cudaGetSymbolAddress((void**)&aop, g_ao);
    cudaGetSymbolAddress((void**)&np,  g_norm);

    const int M = BATCH * NTOK;   // 8192

    // fused q+v projection (norms fused into q epilogue)
    sgemm_dual<<<dim3(16, M / 128), 256>>>(
        x, Wq, bq, qp, Wv, bv, vp, np, M, INNER, DMODEL);

    int smem = (64 * QSTR + 64 * KSTR + 64 * VSTR + 64 * PSTR + 64) * (int)sizeof(float);
    cudaFuncSetAttribute(attn_kernel,
                         cudaFuncAttributeMaxDynamicSharedMemorySize, smem);
    attn_kernel<<<dim3(NTOK / 128, BATCH * HEADS), 128, smem>>>(qp, vp, np, aop);

    // output projection
    sgemm_dual<<<dim3(8, M / 128), 256>>>(
        aop, Wo, bo, out, Wo, bo, out, nullptr, M, DMODEL, INNER);
}